// round 16
// baseline (speedup 1.0000x reference)
#include <cuda_runtime.h>
#include <cuda_fp16.h>
#include <math.h>

#define NN 100000
#define EE 1600000

// ---------------- scratch (static device globals; no allocs allowed) ----------
__device__ __half g_xh[NN * 128];
__device__ __half g_h1h[NN * 128];
__device__ __half g_h2h[NN * 256];
__device__ __half g_h2ah[NN * 256];
__device__ __half g_p64h[NN * 64];
__device__ float  g_dinv[NN];
__device__ int    g_deg[NN];
__device__ int    g_rowptr[NN + 1];
__device__ int    g_cursor[NN];
__device__ int    g_csr[EE];            // src only; coef derived from g_dinv
__device__ int    g_blksum[128];
__device__ int    g_is64;
__device__ __half g_Wph[4 * 256 * 64];
__device__ __half g_Wc0h[128 * 256];
__device__ __half g_Wc1h[256 * 256];

// ---------------- PDL: wait for programmatic-launch dependencies --------------
__device__ __forceinline__ void gdc_wait() {
    asm volatile("griddepcontrol.wait;" ::: "memory");
}

// ---------------- edge index dtype handling ----------------------------------
__device__ __forceinline__ int edge_at(const void* ei, long long idx) {
    if (g_is64) return (int)((const long long*)ei)[idx];
    return ((const int*)ei)[idx];
}

// tiny: detect int64-vs-int32 edge layout (runs FIRST so g_is64 is >=2-back for count)
__global__ void detect_kernel(const int* ei32) {
    if (threadIdx.x == 0) {
        int nz = 0;
        for (int k = 0; k < 64; k++) nz |= ei32[2 * k + 1];
        g_is64 = (nz == 0) ? 1 : 0;   // int64 LE: hi-words all zero
    }
}

__global__ void init_kernel() {
    int i = blockIdx.x * blockDim.x + threadIdx.x;
    if (i < NN) g_deg[i] = 0;
}

// 2 edges per thread; edge loads PRE-wait (is64 from detect, 2-back), atomics post-wait
__global__ void count_kernel(const void* ei, int E) {
    int e = (blockIdx.x * blockDim.x + threadIdx.x) * 2;
    if (e >= E) { gdc_wait(); return; }
    int d0, d1 = -1;
    if (g_is64) {
        const long long* p = (const long long*)ei + E + e;
        d0 = (int)p[0];
        if (e + 1 < E) d1 = (int)p[1];
    } else {
        const int* p = (const int*)ei + E + e;
        d0 = p[0];
        if (e + 1 < E) d1 = p[1];
    }
    gdc_wait();                        // init (zeroed g_deg) must be done
    atomicAdd(&g_deg[d0], 1);
    if (d1 >= 0) atomicAdd(&g_deg[d1], 1);
}

// warp-shuffle block scan (1024 threads, 2 barriers)
__global__ void scan1_kernel() {
    gdc_wait();
    __shared__ int wsum[32];
    int t = threadIdx.x;
    int w = t >> 5, l = t & 31;
    int idx = blockIdx.x * 1024 + t;
    int v = (idx < NN) ? g_deg[idx] : 0;
    if (idx < NN) g_dinv[idx] = rsqrtf((float)v + 1.0f);
    int p = v;
#pragma unroll
    for (int o = 1; o < 32; o <<= 1) {
        int y = __shfl_up_sync(0xffffffffu, p, o);
        if (l >= o) p += y;
    }
    if (l == 31) wsum[w] = p;
    __syncthreads();
    if (w == 0) {
        int s = wsum[l];
        int q = s;
#pragma unroll
        for (int o = 1; o < 32; o <<= 1) {
            int y = __shfl_up_sync(0xffffffffu, q, o);
            if (l >= o) q += y;
        }
        wsum[l] = q - s;
    }
    __syncthreads();
    int excl = wsum[w] + p - v;
    if (idx < NN) g_rowptr[idx] = excl;
    if (t == 1023) g_blksum[blockIdx.x] = wsum[31] + p;
}

// merged scan2+scan3
__global__ void scan23_kernel(int nb) {
    gdc_wait();
    __shared__ int boff[128];
    __shared__ int btot;
    int t = threadIdx.x;
    if (t < 32) {
        int loc[4];
        int sum = 0;
#pragma unroll
        for (int k = 0; k < 4; k++) {
            int i = t * 4 + k;
            int x = (i < nb) ? g_blksum[i] : 0;
            loc[k] = sum;
            sum += x;
        }
        int pre = sum;
#pragma unroll
        for (int o = 1; o < 32; o <<= 1) {
            int y = __shfl_up_sync(0xffffffffu, pre, o);
            if (t >= o) pre += y;
        }
        int excl = pre - sum;
#pragma unroll
        for (int k = 0; k < 4; k++) boff[t * 4 + k] = excl + loc[k];
        if (t == 31) btot = excl + sum;
    }
    __syncthreads();
    int i = blockIdx.x * blockDim.x + t;
    if (i < NN) {
        int r = g_rowptr[i] + boff[i >> 10];
        g_rowptr[i] = r;
        g_cursor[i] = r;
    }
    if (blockIdx.x == 0 && t == 0) g_rowptr[NN] = btot;
}

// 2 edges per thread; edge loads PRE-wait, cursor atomics post-wait
__global__ void fill_kernel(const void* ei, int E) {
    int e = (blockIdx.x * blockDim.x + threadIdx.x) * 2;
    if (e >= E) { gdc_wait(); return; }
    int s0, d0, s1 = -1, d1 = -1;
    if (g_is64) {
        const long long* ps = (const long long*)ei + e;
        const long long* pd = (const long long*)ei + E + e;
        s0 = (int)ps[0]; d0 = (int)pd[0];
        if (e + 1 < E) { s1 = (int)ps[1]; d1 = (int)pd[1]; }
    } else {
        const int* ps = (const int*)ei + e;
        const int* pd = (const int*)ei + E + e;
        s0 = ps[0]; d0 = pd[0];
        if (e + 1 < E) { s1 = ps[1]; d1 = pd[1]; }
    }
    gdc_wait();                        // scan23 (cursor init) must be done
    int pos0 = atomicAdd(&g_cursor[d0], 1);
    g_csr[pos0] = s0;
    if (d1 >= 0) {
        int pos1 = atomicAdd(&g_cursor[d1], 1);
        g_csr[pos1] = s1;
    }
}

// ---------------- one-shot prep: x->half, Wc converts, proj pads ---------------
__global__ void prep_all_kernel(const float* __restrict__ x,
                                const float* __restrict__ Wc0, const float* __restrict__ Wc1,
                                const float* __restrict__ We0, const float* __restrict__ We1,
                                const float* __restrict__ We2, const float* __restrict__ We3) {
    int b = blockIdx.x;
    int t = threadIdx.x;
    if (b < 12500) {
        int i = b * 256 + t;
        float4 v = *(const float4*)&x[i * 4];
        __half2 a = __floats2half2_rn(v.x, v.y);
        __half2 c = __floats2half2_rn(v.z, v.w);
        uint2 u; u.x = *(unsigned*)&a; u.y = *(unsigned*)&c;
        *(uint2*)&g_xh[i * 4] = u;
        return;
    }
    b -= 12500;
    if (b < 32) {
        int i = b * 256 + t;
        float4 v = *(const float4*)&Wc0[i * 4];
        __half2 a = __floats2half2_rn(v.x, v.y);
        __half2 c = __floats2half2_rn(v.z, v.w);
        uint2 u; u.x = *(unsigned*)&a; u.y = *(unsigned*)&c;
        *(uint2*)&g_Wc0h[i * 4] = u;
        return;
    }
    b -= 32;
    if (b < 64) {
        int i = b * 256 + t;
        float4 v = *(const float4*)&Wc1[i * 4];
        __half2 a = __floats2half2_rn(v.x, v.y);
        __half2 c = __floats2half2_rn(v.z, v.w);
        uint2 u; u.x = *(unsigned*)&a; u.y = *(unsigned*)&c;
        *(uint2*)&g_Wc1h[i * 4] = u;
        return;
    }
    b -= 64;
    const float* Ws[4] = {We0, We1, We2, We3};
    const int   nblk[4] = {32, 32, 64, 64};
    for (int w = 0; w < 4; w++) {
        if (b < nblk[w]) {
            int idx = b * 256 + t;
            int k = idx >> 6, j = idx & 63;
            g_Wph[w * 256 * 64 + idx] = __float2half((j < 40) ? Ws[w][k * 40 + j] : 0.0f);
            return;
        }
        b -= nblk[w];
    }
}

// ---------------- half accumulate helpers --------------------------------------
__device__ __forceinline__ void acc_u2(float* a, unsigned lo, unsigned hi, float c) {
    float2 f0 = __half22float2(*reinterpret_cast<__half2*>(&lo));
    float2 f1 = __half22float2(*reinterpret_cast<__half2*>(&hi));
    a[0] = fmaf(c, f0.x, a[0]);
    a[1] = fmaf(c, f0.y, a[1]);
    a[2] = fmaf(c, f1.x, a[2]);
    a[3] = fmaf(c, f1.y, a[3]);
}

__device__ __forceinline__ void acc_u4(float* a, uint4 u, float c) {
    acc_u2(a,     u.x, u.y, c);
    acc_u2(a + 4, u.z, u.w, c);
}

// ---------------- aggregation: LANES lanes/node, uint4 gather, 4-edge pipe ----
template <int LANES>
__global__ void agg_u4_kernel(const __half* __restrict__ h, __half* __restrict__ out) {
    gdc_wait();
    int gid  = (blockIdx.x * blockDim.x + threadIdx.x) / LANES;
    int lane = threadIdx.x & (LANES - 1);
    if (gid >= NN) return;
    const uint4* hv = (const uint4*)h;
    float acc[8];
#pragma unroll
    for (int i = 0; i < 8; i++) acc[i] = 0.0f;
    float dinv0 = g_dinv[gid];
    {
        uint4 u = hv[(long long)gid * LANES + lane];
        acc_u4(acc, u, dinv0);
    }
    int beg = g_rowptr[gid], end = g_rowptr[gid + 1];
    int j = beg;
    for (; j + 3 < end; j += 4) {
        int s0 = g_csr[j],     s1 = g_csr[j + 1];
        int s2 = g_csr[j + 2], s3 = g_csr[j + 3];
        float c0 = __ldg(&g_dinv[s0]);
        float c1 = __ldg(&g_dinv[s1]);
        float c2 = __ldg(&g_dinv[s2]);
        float c3 = __ldg(&g_dinv[s3]);
        uint4 v0 = __ldg(&hv[(long long)s0 * LANES + lane]);
        uint4 v1 = __ldg(&hv[(long long)s1 * LANES + lane]);
        uint4 v2 = __ldg(&hv[(long long)s2 * LANES + lane]);
        uint4 v3 = __ldg(&hv[(long long)s3 * LANES + lane]);
        acc_u4(acc, v0, c0);
        acc_u4(acc, v1, c1);
        acc_u4(acc, v2, c2);
        acc_u4(acc, v3, c3);
    }
    for (; j < end; j++) {
        int s = g_csr[j];
        float c = __ldg(&g_dinv[s]);
        uint4 v = __ldg(&hv[(long long)s * LANES + lane]);
        acc_u4(acc, v, c);
    }
    __half2 p0 = __floats2half2_rn(acc[0] * dinv0, acc[1] * dinv0);
    __half2 p1 = __floats2half2_rn(acc[2] * dinv0, acc[3] * dinv0);
    __half2 p2 = __floats2half2_rn(acc[4] * dinv0, acc[5] * dinv0);
    __half2 p3 = __floats2half2_rn(acc[6] * dinv0, acc[7] * dinv0);
    uint4 r;
    r.x = *(unsigned*)&p0; r.y = *(unsigned*)&p1;
    r.z = *(unsigned*)&p2; r.w = *(unsigned*)&p3;
    ((uint4*)out)[(long long)gid * LANES + lane] = r;
}

// ---------------- mma/ldmatrix/cp.async helpers -------------------------------
__device__ __forceinline__ unsigned smem_u32(const void* p) {
    return (unsigned)__cvta_generic_to_shared(p);
}

__device__ __forceinline__ void cp16(unsigned dst, const void* src) {
    asm volatile("cp.async.cg.shared.global [%0], [%1], 16;" :: "r"(dst), "l"(src));
}

__device__ __forceinline__ void cp_commit() {
    asm volatile("cp.async.commit_group;");
}

template <int N>
__device__ __forceinline__ void cp_wait() {
    asm volatile("cp.async.wait_group %0;" :: "n"(N));
}

__device__ __forceinline__ void ldsm_x4(unsigned& r0, unsigned& r1, unsigned& r2, unsigned& r3,
                                        unsigned addr) {
    asm volatile("ldmatrix.sync.aligned.m8n8.x4.shared.b16 {%0,%1,%2,%3}, [%4];"
                 : "=r"(r0), "=r"(r1), "=r"(r2), "=r"(r3) : "r"(addr));
}

__device__ __forceinline__ void ldsm_x4_t(unsigned& r0, unsigned& r1, unsigned& r2, unsigned& r3,
                                          unsigned addr) {
    asm volatile("ldmatrix.sync.aligned.m8n8.x4.trans.shared.b16 {%0,%1,%2,%3}, [%4];"
                 : "=r"(r0), "=r"(r1), "=r"(r2), "=r"(r3) : "r"(addr));
}

__device__ __forceinline__ void mma_f16(float* c, const unsigned* a, const unsigned* b) {
    asm volatile(
        "mma.sync.aligned.m16n8k16.row.col.f32.f16.f16.f32 "
        "{%0,%1,%2,%3}, {%4,%5,%6,%7}, {%8,%9}, {%0,%1,%2,%3};"
        : "+f"(c[0]), "+f"(c[1]), "+f"(c[2]), "+f"(c[3])
        : "r"(a[0]), "r"(a[1]), "r"(a[2]), "r"(a[3]), "r"(b[0]), "r"(b[1]));
}

// ---------------- fp16 GEMM (BM=128,BN=64,BK=32; 256 thr; 2-stage cp.async) ----
// GDC: PDL kernel — B (weights) staged pre-wait; A waits on immediate pred.
template <int K, int M, bool BIAS_RELU, bool OUTH, bool SMAX, bool GDC>
__global__ void __launch_bounds__(256)
hgemm_kernel(const __half* __restrict__ A, const __half* __restrict__ W,
             const float* __restrict__ bias, void* __restrict__ Cv,
             float* __restrict__ out, int layer) {
    constexpr int NS = K / 32;
    constexpr int A_ELEM = 128 * 40;
    constexpr int B_ELEM = 32 * 72;
    constexpr int PIPE_BYTES = 2 * (A_ELEM + B_ELEM) * 2;
    constexpr int PS_BYTES = 128 * 66 * 4;
    constexpr int SMEM_BYTES = (SMAX && PS_BYTES > PIPE_BYTES) ? PS_BYTES : PIPE_BYTES;
    __shared__ __align__(16) unsigned char smemraw[SMEM_BYTES];
    __half* Asb = reinterpret_cast<__half*>(smemraw);
    __half* Bsb = reinterpret_cast<__half*>(smemraw + 2 * A_ELEM * 2);
    float  (*ps)[66] = reinterpret_cast<float(*)[66]>(smemraw);

    const int t = threadIdx.x;
    const int lane = t & 31;
    const int warp = t >> 5;
    const int wm = warp & 3;
    const int wn = warp >> 2;
    const int bm = blockIdx.x * 128;
    const int bn = blockIdx.y * 64;

    float acc[2][4][4];
#pragma unroll
    for (int mi = 0; mi < 2; mi++)
#pragma unroll
        for (int ni = 0; ni < 4; ni++)
#pragma unroll
            for (int r = 0; r < 4; r++) acc[mi][ni][r] = 0.0f;

    const int arow0 = t >> 2, ac4_0 = (t & 3) * 8;
    const int brow  = t >> 3, bc8   = (t & 7) * 8;

    auto stageB = [&](int s, int buf) {
        __half* Bs = Bsb + buf * B_ELEM;
        int k0 = s * 32;
        cp16(smem_u32(&Bs[brow * 72 + bc8]), &W[(long long)(k0 + brow) * M + bn + bc8]);
    };
    auto stageA = [&](int s, int buf) {
        __half* As = Asb + buf * A_ELEM;
        int k0 = s * 32;
#pragma unroll
        for (int r = 0; r < 2; r++) {
            int row = arow0 + r * 64;
            int grow = bm + row; if (grow > NN - 1) grow = NN - 1;
            cp16(smem_u32(&As[row * 40 + ac4_0]), &A[(long long)grow * K + k0 + ac4_0]);
        }
    };

    // B is weights (>=2-back / event-joined): safe pre-wait. A needs the wait.
    stageB(0, 0);
    if (GDC) gdc_wait();
    stageA(0, 0);
    cp_commit();

    for (int s = 0; s < NS; s++) {
        if (s + 1 < NS) {
            stageB(s + 1, (s + 1) & 1);
            stageA(s + 1, (s + 1) & 1);
            cp_commit();
            cp_wait<1>();
        } else {
            cp_wait<0>();
        }
        __syncthreads();
        const __half (*As)[40] = reinterpret_cast<const __half(*)[40]>(Asb + (s & 1) * A_ELEM);
        const __half (*Bs)[72] = reinterpret_cast<const __half(*)[72]>(Bsb + (s & 1) * B_ELEM);
#pragma unroll
        for (int ks = 0; ks < 2; ks++) {
            unsigned a[2][4], b[4][2];
#pragma unroll
            for (int mi = 0; mi < 2; mi++) {
                int row = wm * 32 + mi * 16 + (lane & 15);
                int col = ks * 16 + (lane >> 4) * 8;
                ldsm_x4(a[mi][0], a[mi][1], a[mi][2], a[mi][3], smem_u32(&As[row][col]));
            }
#pragma unroll
            for (int p = 0; p < 2; p++) {
                int row = ks * 16 + ((lane >> 3) & 1) * 8 + (lane & 7);
                int col = wn * 32 + p * 16 + (lane >> 4) * 8;
                ldsm_x4_t(b[2 * p][0], b[2 * p][1], b[2 * p + 1][0], b[2 * p + 1][1],
                          smem_u32(&Bs[row][col]));
            }
#pragma unroll
            for (int mi = 0; mi < 2; mi++)
#pragma unroll
                for (int ni = 0; ni < 4; ni++)
                    mma_f16(acc[mi][ni], a[mi], b[ni]);
        }
        __syncthreads();
    }

    if (SMAX) {
#pragma unroll
        for (int mi = 0; mi < 2; mi++)
#pragma unroll
            for (int ni = 0; ni < 4; ni++) {
                int col = wn * 32 + ni * 8 + 2 * (lane & 3);
#pragma unroll
                for (int h = 0; h < 2; h++) {
                    int row = wm * 32 + mi * 16 + (lane >> 2) + h * 8;
                    *(float2*)&ps[row][col] =
                        make_float2(acc[mi][ni][2 * h], acc[mi][ni][2 * h + 1]);
                }
            }
        __syncthreads();
        int gi = t >> 3, sub = t & 7;
#pragma unroll
        for (int pass = 0; pass < 4; pass++) {
            int r = pass * 32 + gi;
            int grow = bm + r;
            float v[5];
#pragma unroll
            for (int i = 0; i < 5; i++) v[i] = ps[r][sub + 8 * i] + bias[sub + 8 * i];
            float m = fmaxf(fmaxf(fmaxf(v[0], v[1]), fmaxf(v[2], v[3])), v[4]);
#pragma unroll
            for (int o = 1; o < 8; o <<= 1) m = fmaxf(m, __shfl_xor_sync(0xffffffffu, m, o));
            float s2 = 0.0f;
#pragma unroll
            for (int i = 0; i < 5; i++) s2 += expf(v[i] - m);
#pragma unroll
            for (int o = 1; o < 8; o <<= 1) s2 += __shfl_xor_sync(0xffffffffu, s2, o);
            float lse = m + logf(s2);
            if (grow < NN) {
                float* op = out + (long long)grow * 160 + layer * 40;
#pragma unroll
                for (int i = 0; i < 5; i++) op[sub + 8 * i] = v[i] - lse;
            }
        }
    } else {
#pragma unroll
        for (int mi = 0; mi < 2; mi++) {
#pragma unroll
            for (int ni = 0; ni < 4; ni++) {
                int col = bn + wn * 32 + ni * 8 + 2 * (lane & 3);
                float bv0 = 0.f, bv1 = 0.f;
                if (BIAS_RELU) { bv0 = bias[col]; bv1 = bias[col + 1]; }
#pragma unroll
                for (int h = 0; h < 2; h++) {
                    int row = bm + wm * 32 + mi * 16 + (lane >> 2) + h * 8;
                    if (row < NN) {
                        float v0 = acc[mi][ni][2 * h];
                        float v1 = acc[mi][ni][2 * h + 1];
                        if (BIAS_RELU) {
                            v0 = fmaxf(v0 + bv0, 0.0f);
                            v1 = fmaxf(v1 + bv1, 0.0f);
                        }
                        if (OUTH) {
                            __half2 p = __floats2half2_rn(v0, v1);
                            *(__half2*)&((__half*)Cv)[(long long)row * M + col] = p;
                        } else {
                            *(float2*)&((float*)Cv)[(long long)row * M + col] = make_float2(v0, v1);
                        }
                    }
                }
            }
        }
    }
}

// ---------------- fused Wc1 + relu + proj3 -------------------------------------
#define WP_PIPE_BYTES 54272
#define WP_SMEM_BYTES 121856

__global__ void __launch_bounds__(512)
wc1_proj_kernel(const __half* __restrict__ A,      // h2a [NN,256]
                const __half* __restrict__ W1,     // Wc1 [256,256] half
                const float* __restrict__ b1,      // bc1 [256]
                const __half* __restrict__ Wp,     // padded We3 [256,64] half
                __half* __restrict__ P) {          // p64h [NN,64]
    extern __shared__ __align__(16) unsigned char dsm[];
    __half* As0 = (__half*)dsm;                         // 2 stages 128x40
    __half* Bs0 = (__half*)(dsm + 2 * 128 * 40 * 2);    // 2 stages 32x264
    __half* Wps = (__half*)dsm;                         // phase2: 256x72
    __half* Hs  = (__half*)(dsm + WP_PIPE_BYTES);       // 128x264

    const int t = threadIdx.x;
    const int lane = t & 31;
    const int warp = t >> 5;       // 0..15
    const int wm = warp & 3;       // 4 row slabs x32
    const int wn = warp >> 2;      // 4 col slabs x64
    const int bm = blockIdx.x * 128;

    float acc[2][8][4];
#pragma unroll
    for (int mi = 0; mi < 2; mi++)
#pragma unroll
        for (int ni = 0; ni < 8; ni++)
#pragma unroll
            for (int r = 0; r < 4; r++) acc[mi][ni][r] = 0.0f;

    const int arow = t >> 2, ac = (t & 3) * 8;

    auto stageB = [&](int s, int buf) {
        __half* Bs = Bs0 + buf * 32 * 264;
        int k0 = s * 32;
#pragma unroll
        for (int r = 0; r < 2; r++) {
            int idx = t + r * 512;
            int kk = idx >> 5, c8 = (idx & 31) * 8;
            cp16(smem_u32(&Bs[kk * 264 + c8]), &W1[(long long)(k0 + kk) * 256 + c8]);
        }
    };
    auto stageA = [&](int s, int buf) {
        __half* As = As0 + buf * 128 * 40;
        int k0 = s * 32;
        int grow = bm + arow; if (grow > NN - 1) grow = NN - 1;
        cp16(smem_u32(&As[arow * 40 + ac]), &A[(long long)grow * 256 + k0 + ac]);
    };

    // W1 (weights, event-joined prep): safe pre-wait. A (h2ah from agg2) needs wait.
    stageB(0, 0);
    gdc_wait();
    stageA(0, 0);
    cp_commit();

    for (int s = 0; s < 8; s++) {
        if (s + 1 < 8) {
            stageB(s + 1, (s + 1) & 1);
            stageA(s + 1, (s + 1) & 1);
            cp_commit();
            cp_wait<1>();
        } else {
            cp_wait<0>();
        }
        __syncthreads();
        const __half* As = As0 + (s & 1) * 128 * 40;
        const __half* Bs = Bs0 + (s & 1) * 32 * 264;
#pragma unroll
        for (int ks = 0; ks < 2; ks++) {
            unsigned a[2][4], b[8][2];
#pragma unroll
            for (int mi = 0; mi < 2; mi++) {
                int row = wm * 32 + mi * 16 + (lane & 15);
                int col = ks * 16 + (lane >> 4) * 8;
                ldsm_x4(a[mi][0], a[mi][1], a[mi][2], a[mi][3], smem_u32(&As[row * 40 + col]));
            }
#pragma unroll
            for (int p = 0; p < 4; p++) {
                int row = ks * 16 + ((lane >> 3) & 1) * 8 + (lane & 7);
                int col = wn * 64 + p * 16 + (lane >> 4) * 8;
                ldsm_x4_t(b[2 * p][0], b[2 * p][1], b[2 * p + 1][0], b[2 * p + 1][1],
                          smem_u32(&Bs[row * 264 + col]));
            }
#pragma unroll
            for (int mi = 0; mi < 2; mi++)
#pragma unroll
                for (int ni = 0; ni < 8; ni++)
                    mma_f16(acc[mi][ni], a[mi], b[ni]);
        }
        __syncthreads();
    }

    // phase boundary: relu(acc + bias) -> Hs (half)
#pragma unroll
    for (int mi = 0; mi < 2; mi++) {
#pragma unroll
        for (int ni = 0; ni < 8; ni++) {
            int col = wn * 64 + ni * 8 + 2 * (lane & 3);
            float bv0 = b1[col], bv1 = b1[col + 1];
#pragma unroll
            for (int h = 0; h < 2; h++) {
                int row = wm * 32 + mi * 16 + (lane >> 2) + h * 8;
                float v0 = fmaxf(acc[mi][ni][2 * h] + bv0, 0.0f);
                float v1 = fmaxf(acc[mi][ni][2 * h + 1] + bv1, 0.0f);
                *(__half2*)&Hs[row * 264 + col] = __floats2half2_rn(v0, v1);
            }
        }
    }
    __syncthreads();

    // stage Wp3 [256,64] into Wps (stride 72) — pipe region free now
#pragma unroll
    for (int r = 0; r < 4; r++) {
        int idx = t + r * 512;
        int kk = idx >> 3, c8 = (idx & 7) * 8;
        cp16(smem_u32(&Wps[kk * 72 + c8]), &Wp[(long long)kk * 64 + c8]);
    }
    cp_commit();
    cp_wait<0>();
    __syncthreads();

    // phase 2: H @ Wp3 -> P
    const int wm2 = warp & 7;      // 8 row groups x16
    const int wn2 = warp >> 3;     // 2 col groups x32
    float acc2[4][4];
#pragma unroll
    for (int ni = 0; ni < 4; ni++)
#pragma unroll
        for (int r = 0; r < 4; r++) acc2[ni][r] = 0.0f;

#pragma unroll
    for (int kc = 0; kc < 16; kc++) {
        unsigned a[4], b[4][2];
        {
            int row = wm2 * 16 + (lane & 15);
            int col = kc * 16 + (lane >> 4) * 8;
            ldsm_x4(a[0], a[1], a[2], a[3], smem_u32(&Hs[row * 264 + col]));
        }
#pragma unroll
        for (int p = 0; p < 2; p++) {
            int row = kc * 16 + ((lane >> 3) & 1) * 8 + (lane & 7);
            int col = wn2 * 32 + p * 16 + (lane >> 4) * 8;
            ldsm_x4_t(b[2 * p][0], b[2 * p][1], b[2 * p + 1][0], b[2 * p + 1][1],
                      smem_u32(&Wps[row * 72 + col]));
        }
#pragma unroll
        for (int ni = 0; ni < 4; ni++)
            mma_f16(acc2[ni], a, b[ni]);
    }

#pragma unroll
    for (int ni = 0; ni < 4; ni++) {
        int col = wn2 * 32 + ni * 8 + 2 * (lane & 3);
#pragma unroll
        for (int h = 0; h < 2; h++) {
            int row = bm + wm2 * 16 + (lane >> 2) + h * 8;
            if (row < NN) {
                *(__half2*)&P[(long long)row * 64 + col] =
                    __floats2half2_rn(acc2[ni][2 * h], acc2[ni][2 * h + 1]);
            }
        }
    }
}

// ---------------- last layer: half 40-dim aggregate + bias + log_softmax ------
__global__ void agg40h_kernel(const __half* __restrict__ P, const float* __restrict__ bias,
                              float* __restrict__ out) {
    // rowptr/dinv/csr are >=2-back: safe pre-wait. P (wc1_proj) needs the wait.
    int gid = blockIdx.x * (blockDim.x >> 3) + (threadIdx.x >> 3);
    int t = threadIdx.x & 7;
    bool valid = gid < NN;
    bool cvalid = t < 5;
    float v[8];
#pragma unroll
    for (int i = 0; i < 8; i++) v[i] = 0.0f;
    const uint4* Pv = (const uint4*)P;
    int beg = 0, end = 0;
    float dinv0 = 0.0f;
    if (valid) {
        dinv0 = g_dinv[gid];
        beg = g_rowptr[gid];
        end = g_rowptr[gid + 1];
    }
    gdc_wait();
    if (valid) {
        uint4 u = Pv[gid * 8 + t];
        acc_u4(v, u, dinv0);
    }
    int j = beg;
    for (; j + 3 < end; j += 4) {
        int s0 = g_csr[j],     s1 = g_csr[j + 1];
        int s2 = g_csr[j + 2], s3 = g_csr[j + 3];
        float c0 = __ldg(&g_dinv[s0]);
        float c1 = __ldg(&g_dinv[s1]);
        float c2 = __ldg(&g_dinv[s2]);
        float c3 = __ldg(&g_dinv[s3]);
        uint4 u0 = __ldg(&Pv[s0 * 8 + t]);
        uint4 u1 = __ldg(&Pv[s1 * 8 + t]);
        uint4 u2 = __ldg(&Pv[s2 * 8 + t]);
        uint4 u3 = __ldg(&Pv[s3 * 8 + t]);
        acc_u4(v, u0, c0);
        acc_u4(v, u1, c1);
        acc_u4(v, u2, c2);
        acc_u4(v, u3, c3);
    }
    for (; j < end; j++) {
        int s = g_csr[j];
        float c = __ldg(&g_dinv[s]);
        uint4 u = __ldg(&Pv[s * 8 + t]);
        acc_u4(v, u, c);
    }
    float m = -1e30f;
    if (cvalid) {
#pragma unroll
        for (int i = 0; i < 8; i++) {
            v[i] = v[i] * dinv0 + bias[8 * t + i];
            m = fmaxf(m, v[i]);
        }
    }
#pragma unroll
    for (int o = 1; o < 8; o <<= 1) m = fmaxf(m, __shfl_xor_sync(0xffffffffu, m, o));
    float s = 0.0f;
    if (cvalid) {
#pragma unroll
        for (int i = 0; i < 8; i++) s += expf(v[i] - m);
    }
#pragma unroll
    for (int o = 1; o < 8; o <<= 1) s += __shfl_xor_sync(0xffffffffu, s, o);
    float lse = m + logf(s);
    if (valid && cvalid) {
        float* op = out + (long long)gid * 160 + 120 + 8 * t;
        *(float4*)&op[0] = make_float4(v[0] - lse, v[1] - lse, v[2] - lse, v[3] - lse);
        *(float4*)&op[4] = make_float4(v[4] - lse, v[5] - lse, v[6] - lse, v[7] - lse);
    }
}

// ---------------- PDL launch helper ---------------------------------------------
template <typename Kern, typename... Args>
static void launch_pdl(Kern kern, dim3 grid, dim3 block, size_t smem, cudaStream_t st,
                       Args... args) {
    cudaLaunchConfig_t cfg = {};
    cfg.gridDim = grid;
    cfg.blockDim = block;
    cfg.dynamicSmemBytes = smem;
    cfg.stream = st;
    cudaLaunchAttribute at[1];
    at[0].id = cudaLaunchAttributeProgrammaticStreamSerialization;
    at[0].val.programmaticStreamSerializationAllowed = 1;
    cfg.attrs = at;
    cfg.numAttrs = 1;
    cudaLaunchKernelEx(&cfg, kern, args...);
}

// ---------------- launch -------------------------------------------------------
extern "C" void kernel_launch(void* const* d_in, const int* in_sizes, int n_in,
                              void* d_out, int out_size) {
    const float* x   = (const float*)d_in[0];
    const void*  ei  = d_in[1];
    const float* Wc0 = (const float*)d_in[2];
    const float* bc0 = (const float*)d_in[3];
    const float* Wc1 = (const float*)d_in[4];
    const float* bc1 = (const float*)d_in[5];
    // d_in[6], d_in[7] (Wc2, bc2): dead — final Wc output is never used
    const float* We0 = (const float*)d_in[8];
    const float* be0 = (const float*)d_in[9];
    const float* We1 = (const float*)d_in[10];
    const float* be1 = (const float*)d_in[11];
    const float* We2 = (const float*)d_in[12];
    const float* be2 = (const float*)d_in[13];
    const float* We3 = (const float*)d_in[14];
    const float* be3 = (const float*)d_in[15];
    float* out = (float*)d_out;
    int E = in_sizes[1] / 2;

    __half *xh, *h1h, *h2h, *h2ah, *p64h, *wph, *wc0h, *wc1h;
    cudaGetSymbolAddress((void**)&xh,   g_xh);
    cudaGetSymbolAddress((void**)&h1h,  g_h1h);
    cudaGetSymbolAddress((void**)&h2h,  g_h2h);
    cudaGetSymbolAddress((void**)&h2ah, g_h2ah);
    cudaGetSymbolAddress((void**)&p64h, g_p64h);
    cudaGetSymbolAddress((void**)&wph,  g_Wph);
    cudaGetSymbolAddress((void**)&wc0h, g_Wc0h);
    cudaGetSymbolAddress((void**)&wc1h, g_Wc1h);
    __half* wp0 = wph;
    __half* wp1 = wph + 1 * 256 * 64;
    __half* wp2 = wph + 2 * 256 * 64;
    __half* wp3 = wph + 3 * 256 * 64;

    // allow >48KB dynamic smem for the fused kernel (host attr set; not captured)
    cudaFuncSetAttribute(wc1_proj_kernel, cudaFuncAttributeMaxDynamicSharedMemorySize,
                         WP_SMEM_BYTES);

    static cudaStream_t s1 = nullptr;
    static cudaEvent_t evStart, evPre, evA1, evA2, evS1;
    if (!s1) {
        cudaStreamCreateWithFlags(&s1, cudaStreamNonBlocking);
        cudaEventCreateWithFlags(&evStart, cudaEventDisableTiming);
        cudaEventCreateWithFlags(&evPre,   cudaEventDisableTiming);
        cudaEventCreateWithFlags(&evA1,    cudaEventDisableTiming);
        cudaEventCreateWithFlags(&evA2,    cudaEventDisableTiming);
        cudaEventCreateWithFlags(&evS1,    cudaEventDisableTiming);
    }

    int nb = (NN + 1023) / 1024;
    dim3 g1((NN + 127) / 128, 1);
    dim3 g4((NN + 127) / 128, 4);
    int  gs = (NN + 31) / 32;

    cudaEventRecord(evStart, 0);
    cudaStreamWaitEvent(s1, evStart, 0);

    // s1: all weight/feature prep in ONE kernel, then fused layer-0 projection
    prep_all_kernel<<<12788, 256, 0, s1>>>(x, Wc0, Wc1, We0, We1, We2, We3);
    cudaEventRecord(evPre, s1);
    hgemm_kernel<128, 64, false, false, true, false><<<g1, 256, 0, s1>>>(
        xh, wp0, be0, nullptr, out, 0);

    // main: CSR preprocessing — PDL chain with deferred waits
    detect_kernel<<<1, 32>>>((const int*)ei);
    init_kernel<<<(NN + 255) / 256, 256>>>();
    launch_pdl(count_kernel, dim3((E / 2 + 255) / 256), dim3(256), 0, (cudaStream_t)0, ei, E);
    launch_pdl(scan1_kernel, dim3(nb), dim3(1024), 0, (cudaStream_t)0);
    launch_pdl(scan23_kernel, dim3((NN + 255) / 256), dim3(256), 0, (cudaStream_t)0, nb);
    launch_pdl(fill_kernel, dim3((E / 2 + 255) / 256), dim3(256), 0, (cudaStream_t)0, ei, E);

    // main chain — PDL between successive stages
    cudaStreamWaitEvent(0, evPre, 0);
    launch_pdl(agg_u4_kernel<16>, dim3((NN * 16 + 255) / 256), dim3(256), 0, (cudaStream_t)0,
               (const __half*)xh, h1h);                                   // D=128
    cudaEventRecord(evA1, 0);
    launch_pdl(hgemm_kernel<128, 256, true, true, false, true>, g4, dim3(256), 0, (cudaStream_t)0,
               (const __half*)h1h, (const __half*)wc0h, bc0, (void*)h2h, (float*)nullptr, 0);
    launch_pdl(agg_u4_kernel<32>, dim3((NN * 32 + 255) / 256), dim3(256), 0, (cudaStream_t)0,
               (const __half*)h2h, h2ah);                                 // D=256
    cudaEventRecord(evA2, 0);
    launch_pdl(wc1_proj_kernel, dim3((NN + 127) / 128), dim3(512), WP_SMEM_BYTES, (cudaStream_t)0,
               (const __half*)h2ah, (const __half*)wc1h, bc1, (const __half*)wp3, p64h);
    launch_pdl(agg40h_kernel, dim3(gs), dim3(256), 0, (cudaStream_t)0,
               (const __half*)p64h, be3, out);

    // s1: fused projection layers 1/2 overlap the Wc GEMMs / aggs
    cudaStreamWaitEvent(s1, evA1, 0);
    hgemm_kernel<128, 64, false, false, true, false><<<g1, 256, 0, s1>>>(
        h1h, wp1, be1, nullptr, out, 1);
    cudaStreamWaitEvent(s1, evA2, 0);
    hgemm_kernel<256, 64, false, false, true, false><<<g1, 256, 0, s1>>>(
        h2ah, wp2, be2, nullptr, out, 2);
    cudaEventRecord(evS1, s1);

    cudaStreamWaitEvent(0, evS1, 0);
}

// round 17
// speedup vs baseline: 1.0125x; 1.0125x over previous
#include <cuda_runtime.h>
#include <cuda_fp16.h>
#include <math.h>

#define NN 100000
#define EE 1600000

// ---------------- scratch (static device globals; no allocs allowed) ----------
__device__ __half g_xh[NN * 128];
__device__ __half g_h1h[NN * 128];
__device__ __half g_h2h[NN * 256];
__device__ __half g_h2ah[NN * 256];
__device__ __half g_p64h[NN * 64];
__device__ float  g_dinv[NN];
__device__ int    g_deg[NN];
__device__ int    g_rowptr[NN + 1];
__device__ int    g_cursor[NN];
__device__ int    g_csr[EE];            // src only; coef derived from g_dinv
__device__ int    g_blksum[128];
__device__ int    g_is64;
__device__ __half g_Wph[4 * 256 * 64];
__device__ __half g_Wc0h[128 * 256];
__device__ __half g_Wc1h[256 * 256];

// ---------------- PDL: wait for programmatic-launch dependencies --------------
__device__ __forceinline__ void gdc_wait() {
    asm volatile("griddepcontrol.wait;" ::: "memory");
}

// ---------------- edge index dtype handling ----------------------------------
__device__ __forceinline__ int edge_at(const void* ei, long long idx) {
    if (g_is64) return (int)((const long long*)ei)[idx];
    return ((const int*)ei)[idx];
}

__global__ void init_kernel(const int* ei32) {
    int i = blockIdx.x * blockDim.x + threadIdx.x;
    if (i < NN) g_deg[i] = 0;
    if (blockIdx.x == 0 && threadIdx.x == 0) {
        int nz = 0;
        for (int k = 0; k < 64; k++) nz |= ei32[2 * k + 1];
        g_is64 = (nz == 0) ? 1 : 0;   // int64 LE: hi-words all zero
    }
}

// 2 edges per thread (paired index load)
__global__ void count_kernel(const void* ei, int E) {
    gdc_wait();
    int e = (blockIdx.x * blockDim.x + threadIdx.x) * 2;
    if (e >= E) return;
    int d0, d1 = -1;
    if (g_is64) {
        const long long* p = (const long long*)ei + E + e;
        d0 = (int)p[0];
        if (e + 1 < E) d1 = (int)p[1];
    } else {
        const int* p = (const int*)ei + E + e;
        d0 = p[0];
        if (e + 1 < E) d1 = p[1];
    }
    atomicAdd(&g_deg[d0], 1);
    if (d1 >= 0) atomicAdd(&g_deg[d1], 1);
}

// warp-shuffle block scan (1024 threads, 2 barriers)
__global__ void scan1_kernel() {
    gdc_wait();
    __shared__ int wsum[32];
    int t = threadIdx.x;
    int w = t >> 5, l = t & 31;
    int idx = blockIdx.x * 1024 + t;
    int v = (idx < NN) ? g_deg[idx] : 0;
    if (idx < NN) g_dinv[idx] = rsqrtf((float)v + 1.0f);
    int p = v;
#pragma unroll
    for (int o = 1; o < 32; o <<= 1) {
        int y = __shfl_up_sync(0xffffffffu, p, o);
        if (l >= o) p += y;
    }
    if (l == 31) wsum[w] = p;
    __syncthreads();
    if (w == 0) {
        int s = wsum[l];
        int q = s;
#pragma unroll
        for (int o = 1; o < 32; o <<= 1) {
            int y = __shfl_up_sync(0xffffffffu, q, o);
            if (l >= o) q += y;
        }
        wsum[l] = q - s;
    }
    __syncthreads();
    int excl = wsum[w] + p - v;
    if (idx < NN) g_rowptr[idx] = excl;
    if (t == 1023) g_blksum[blockIdx.x] = wsum[31] + p;
}

// merged scan2+scan3
__global__ void scan23_kernel(int nb) {
    gdc_wait();
    __shared__ int boff[128];
    __shared__ int btot;
    int t = threadIdx.x;
    if (t < 32) {
        int loc[4];
        int sum = 0;
#pragma unroll
        for (int k = 0; k < 4; k++) {
            int i = t * 4 + k;
            int x = (i < nb) ? g_blksum[i] : 0;
            loc[k] = sum;
            sum += x;
        }
        int pre = sum;
#pragma unroll
        for (int o = 1; o < 32; o <<= 1) {
            int y = __shfl_up_sync(0xffffffffu, pre, o);
            if (t >= o) pre += y;
        }
        int excl = pre - sum;
#pragma unroll
        for (int k = 0; k < 4; k++) boff[t * 4 + k] = excl + loc[k];
        if (t == 31) btot = excl + sum;
    }
    __syncthreads();
    int i = blockIdx.x * blockDim.x + t;
    if (i < NN) {
        int r = g_rowptr[i] + boff[i >> 10];
        g_rowptr[i] = r;
        g_cursor[i] = r;
    }
    if (blockIdx.x == 0 && t == 0) g_rowptr[NN] = btot;
}

// 2 edges per thread
__global__ void fill_kernel(const void* ei, int E) {
    gdc_wait();
    int e = (blockIdx.x * blockDim.x + threadIdx.x) * 2;
    if (e >= E) return;
    int s0, d0, s1 = -1, d1 = -1;
    if (g_is64) {
        const long long* ps = (const long long*)ei + e;
        const long long* pd = (const long long*)ei + E + e;
        s0 = (int)ps[0]; d0 = (int)pd[0];
        if (e + 1 < E) { s1 = (int)ps[1]; d1 = (int)pd[1]; }
    } else {
        const int* ps = (const int*)ei + e;
        const int* pd = (const int*)ei + E + e;
        s0 = ps[0]; d0 = pd[0];
        if (e + 1 < E) { s1 = ps[1]; d1 = pd[1]; }
    }
    int pos0 = atomicAdd(&g_cursor[d0], 1);
    g_csr[pos0] = s0;
    if (d1 >= 0) {
        int pos1 = atomicAdd(&g_cursor[d1], 1);
        g_csr[pos1] = s1;
    }
}

// ---------------- one-shot prep: x->half, Wc converts, proj pads ---------------
__global__ void prep_all_kernel(const float* __restrict__ x,
                                const float* __restrict__ Wc0, const float* __restrict__ Wc1,
                                const float* __restrict__ We0, const float* __restrict__ We1,
                                const float* __restrict__ We2, const float* __restrict__ We3) {
    int b = blockIdx.x;
    int t = threadIdx.x;
    if (b < 12500) {
        int i = b * 256 + t;
        float4 v = *(const float4*)&x[i * 4];
        __half2 a = __floats2half2_rn(v.x, v.y);
        __half2 c = __floats2half2_rn(v.z, v.w);
        uint2 u; u.x = *(unsigned*)&a; u.y = *(unsigned*)&c;
        *(uint2*)&g_xh[i * 4] = u;
        return;
    }
    b -= 12500;
    if (b < 32) {
        int i = b * 256 + t;
        float4 v = *(const float4*)&Wc0[i * 4];
        __half2 a = __floats2half2_rn(v.x, v.y);
        __half2 c = __floats2half2_rn(v.z, v.w);
        uint2 u; u.x = *(unsigned*)&a; u.y = *(unsigned*)&c;
        *(uint2*)&g_Wc0h[i * 4] = u;
        return;
    }
    b -= 32;
    if (b < 64) {
        int i = b * 256 + t;
        float4 v = *(const float4*)&Wc1[i * 4];
        __half2 a = __floats2half2_rn(v.x, v.y);
        __half2 c = __floats2half2_rn(v.z, v.w);
        uint2 u; u.x = *(unsigned*)&a; u.y = *(unsigned*)&c;
        *(uint2*)&g_Wc1h[i * 4] = u;
        return;
    }
    b -= 64;
    const float* Ws[4] = {We0, We1, We2, We3};
    const int   nblk[4] = {32, 32, 64, 64};
    for (int w = 0; w < 4; w++) {
        if (b < nblk[w]) {
            int idx = b * 256 + t;
            int k = idx >> 6, j = idx & 63;
            g_Wph[w * 256 * 64 + idx] = __float2half((j < 40) ? Ws[w][k * 40 + j] : 0.0f);
            return;
        }
        b -= nblk[w];
    }
}

// ---------------- half accumulate helpers --------------------------------------
__device__ __forceinline__ void acc_u2(float* a, unsigned lo, unsigned hi, float c) {
    float2 f0 = __half22float2(*reinterpret_cast<__half2*>(&lo));
    float2 f1 = __half22float2(*reinterpret_cast<__half2*>(&hi));
    a[0] = fmaf(c, f0.x, a[0]);
    a[1] = fmaf(c, f0.y, a[1]);
    a[2] = fmaf(c, f1.x, a[2]);
    a[3] = fmaf(c, f1.y, a[3]);
}

__device__ __forceinline__ void acc_u4(float* a, uint4 u, float c) {
    acc_u2(a,     u.x, u.y, c);
    acc_u2(a + 4, u.z, u.w, c);
}

// ---------------- aggregation: LANES lanes/node, uint4 gather, 4-edge pipe ----
template <int LANES>
__global__ void agg_u4_kernel(const __half* __restrict__ h, __half* __restrict__ out) {
    gdc_wait();
    int gid  = (blockIdx.x * blockDim.x + threadIdx.x) / LANES;
    int lane = threadIdx.x & (LANES - 1);
    if (gid >= NN) return;
    const uint4* hv = (const uint4*)h;
    float acc[8];
#pragma unroll
    for (int i = 0; i < 8; i++) acc[i] = 0.0f;
    float dinv0 = g_dinv[gid];
    {
        uint4 u = hv[(long long)gid * LANES + lane];
        acc_u4(acc, u, dinv0);
    }
    int beg = g_rowptr[gid], end = g_rowptr[gid + 1];
    int j = beg;
    for (; j + 3 < end; j += 4) {
        int s0 = g_csr[j],     s1 = g_csr[j + 1];
        int s2 = g_csr[j + 2], s3 = g_csr[j + 3];
        float c0 = __ldg(&g_dinv[s0]);
        float c1 = __ldg(&g_dinv[s1]);
        float c2 = __ldg(&g_dinv[s2]);
        float c3 = __ldg(&g_dinv[s3]);
        uint4 v0 = __ldg(&hv[(long long)s0 * LANES + lane]);
        uint4 v1 = __ldg(&hv[(long long)s1 * LANES + lane]);
        uint4 v2 = __ldg(&hv[(long long)s2 * LANES + lane]);
        uint4 v3 = __ldg(&hv[(long long)s3 * LANES + lane]);
        acc_u4(acc, v0, c0);
        acc_u4(acc, v1, c1);
        acc_u4(acc, v2, c2);
        acc_u4(acc, v3, c3);
    }
    for (; j < end; j++) {
        int s = g_csr[j];
        float c = __ldg(&g_dinv[s]);
        uint4 v = __ldg(&hv[(long long)s * LANES + lane]);
        acc_u4(acc, v, c);
    }
    __half2 p0 = __floats2half2_rn(acc[0] * dinv0, acc[1] * dinv0);
    __half2 p1 = __floats2half2_rn(acc[2] * dinv0, acc[3] * dinv0);
    __half2 p2 = __floats2half2_rn(acc[4] * dinv0, acc[5] * dinv0);
    __half2 p3 = __floats2half2_rn(acc[6] * dinv0, acc[7] * dinv0);
    uint4 r;
    r.x = *(unsigned*)&p0; r.y = *(unsigned*)&p1;
    r.z = *(unsigned*)&p2; r.w = *(unsigned*)&p3;
    ((uint4*)out)[(long long)gid * LANES + lane] = r;
}

// ---------------- mma/ldmatrix/cp.async helpers -------------------------------
__device__ __forceinline__ unsigned smem_u32(const void* p) {
    return (unsigned)__cvta_generic_to_shared(p);
}

__device__ __forceinline__ void cp16(unsigned dst, const void* src) {
    asm volatile("cp.async.cg.shared.global [%0], [%1], 16;" :: "r"(dst), "l"(src));
}

__device__ __forceinline__ void cp_commit() {
    asm volatile("cp.async.commit_group;");
}

template <int N>
__device__ __forceinline__ void cp_wait() {
    asm volatile("cp.async.wait_group %0;" :: "n"(N));
}

__device__ __forceinline__ void ldsm_x4(unsigned& r0, unsigned& r1, unsigned& r2, unsigned& r3,
                                        unsigned addr) {
    asm volatile("ldmatrix.sync.aligned.m8n8.x4.shared.b16 {%0,%1,%2,%3}, [%4];"
                 : "=r"(r0), "=r"(r1), "=r"(r2), "=r"(r3) : "r"(addr));
}

__device__ __forceinline__ void ldsm_x4_t(unsigned& r0, unsigned& r1, unsigned& r2, unsigned& r3,
                                          unsigned addr) {
    asm volatile("ldmatrix.sync.aligned.m8n8.x4.trans.shared.b16 {%0,%1,%2,%3}, [%4];"
                 : "=r"(r0), "=r"(r1), "=r"(r2), "=r"(r3) : "r"(addr));
}

__device__ __forceinline__ void mma_f16(float* c, const unsigned* a, const unsigned* b) {
    asm volatile(
        "mma.sync.aligned.m16n8k16.row.col.f32.f16.f16.f32 "
        "{%0,%1,%2,%3}, {%4,%5,%6,%7}, {%8,%9}, {%0,%1,%2,%3};"
        : "+f"(c[0]), "+f"(c[1]), "+f"(c[2]), "+f"(c[3])
        : "r"(a[0]), "r"(a[1]), "r"(a[2]), "r"(a[3]), "r"(b[0]), "r"(b[1]));
}

// ---------------- fp16 GEMM (BM=128,BN=64,BK=32; 256 thr; 2-stage cp.async) ----
// GDC: wait for programmatic dependencies before touching A (main-stream only)
template <int K, int M, bool BIAS_RELU, bool OUTH, bool SMAX, bool GDC>
__global__ void __launch_bounds__(256)
hgemm_kernel(const __half* __restrict__ A, const __half* __restrict__ W,
             const float* __restrict__ bias, void* __restrict__ Cv,
             float* __restrict__ out, int layer) {
    if (GDC) gdc_wait();
    constexpr int NS = K / 32;
    constexpr int A_ELEM = 128 * 40;
    constexpr int B_ELEM = 32 * 72;
    constexpr int PIPE_BYTES = 2 * (A_ELEM + B_ELEM) * 2;
    constexpr int PS_BYTES = 128 * 66 * 4;
    constexpr int SMEM_BYTES = (SMAX && PS_BYTES > PIPE_BYTES) ? PS_BYTES : PIPE_BYTES;
    __shared__ __align__(16) unsigned char smemraw[SMEM_BYTES];
    __half* Asb = reinterpret_cast<__half*>(smemraw);
    __half* Bsb = reinterpret_cast<__half*>(smemraw + 2 * A_ELEM * 2);
    float  (*ps)[66] = reinterpret_cast<float(*)[66]>(smemraw);

    const int t = threadIdx.x;
    const int lane = t & 31;
    const int warp = t >> 5;
    const int wm = warp & 3;
    const int wn = warp >> 2;
    const int bm = blockIdx.x * 128;
    const int bn = blockIdx.y * 64;

    float acc[2][4][4];
#pragma unroll
    for (int mi = 0; mi < 2; mi++)
#pragma unroll
        for (int ni = 0; ni < 4; ni++)
#pragma unroll
            for (int r = 0; r < 4; r++) acc[mi][ni][r] = 0.0f;

    const int arow0 = t >> 2, ac4_0 = (t & 3) * 8;
    const int brow  = t >> 3, bc8   = (t & 7) * 8;

    auto stage = [&](int s, int buf) {
        __half* As = Asb + buf * A_ELEM;
        __half* Bs = Bsb + buf * B_ELEM;
        int k0 = s * 32;
#pragma unroll
        for (int r = 0; r < 2; r++) {
            int row = arow0 + r * 64;
            int grow = bm + row; if (grow > NN - 1) grow = NN - 1;
            cp16(smem_u32(&As[row * 40 + ac4_0]), &A[(long long)grow * K + k0 + ac4_0]);
        }
        cp16(smem_u32(&Bs[brow * 72 + bc8]), &W[(long long)(k0 + brow) * M + bn + bc8]);
    };

    stage(0, 0);
    cp_commit();

    for (int s = 0; s < NS; s++) {
        if (s + 1 < NS) {
            stage(s + 1, (s + 1) & 1);
            cp_commit();
            cp_wait<1>();
        } else {
            cp_wait<0>();
        }
        __syncthreads();
        const __half (*As)[40] = reinterpret_cast<const __half(*)[40]>(Asb + (s & 1) * A_ELEM);
        const __half (*Bs)[72] = reinterpret_cast<const __half(*)[72]>(Bsb + (s & 1) * B_ELEM);
#pragma unroll
        for (int ks = 0; ks < 2; ks++) {
            unsigned a[2][4], b[4][2];
#pragma unroll
            for (int mi = 0; mi < 2; mi++) {
                int row = wm * 32 + mi * 16 + (lane & 15);
                int col = ks * 16 + (lane >> 4) * 8;
                ldsm_x4(a[mi][0], a[mi][1], a[mi][2], a[mi][3], smem_u32(&As[row][col]));
            }
#pragma unroll
            for (int p = 0; p < 2; p++) {
                int row = ks * 16 + ((lane >> 3) & 1) * 8 + (lane & 7);
                int col = wn * 32 + p * 16 + (lane >> 4) * 8;
                ldsm_x4_t(b[2 * p][0], b[2 * p][1], b[2 * p + 1][0], b[2 * p + 1][1],
                          smem_u32(&Bs[row][col]));
            }
#pragma unroll
            for (int mi = 0; mi < 2; mi++)
#pragma unroll
                for (int ni = 0; ni < 4; ni++)
                    mma_f16(acc[mi][ni], a[mi], b[ni]);
        }
        __syncthreads();
    }

    if (SMAX) {
#pragma unroll
        for (int mi = 0; mi < 2; mi++)
#pragma unroll
            for (int ni = 0; ni < 4; ni++) {
                int col = wn * 32 + ni * 8 + 2 * (lane & 3);
#pragma unroll
                for (int h = 0; h < 2; h++) {
                    int row = wm * 32 + mi * 16 + (lane >> 2) + h * 8;
                    *(float2*)&ps[row][col] =
                        make_float2(acc[mi][ni][2 * h], acc[mi][ni][2 * h + 1]);
                }
            }
        __syncthreads();
        int gi = t >> 3, sub = t & 7;
#pragma unroll
        for (int pass = 0; pass < 4; pass++) {
            int r = pass * 32 + gi;
            int grow = bm + r;
            float v[5];
#pragma unroll
            for (int i = 0; i < 5; i++) v[i] = ps[r][sub + 8 * i] + bias[sub + 8 * i];
            float m = fmaxf(fmaxf(fmaxf(v[0], v[1]), fmaxf(v[2], v[3])), v[4]);
#pragma unroll
            for (int o = 1; o < 8; o <<= 1) m = fmaxf(m, __shfl_xor_sync(0xffffffffu, m, o));
            float s2 = 0.0f;
#pragma unroll
            for (int i = 0; i < 5; i++) s2 += expf(v[i] - m);
#pragma unroll
            for (int o = 1; o < 8; o <<= 1) s2 += __shfl_xor_sync(0xffffffffu, s2, o);
            float lse = m + logf(s2);
            if (grow < NN) {
                float* op = out + (long long)grow * 160 + layer * 40;
#pragma unroll
                for (int i = 0; i < 5; i++) op[sub + 8 * i] = v[i] - lse;
            }
        }
    } else {
#pragma unroll
        for (int mi = 0; mi < 2; mi++) {
#pragma unroll
            for (int ni = 0; ni < 4; ni++) {
                int col = bn + wn * 32 + ni * 8 + 2 * (lane & 3);
                float bv0 = 0.f, bv1 = 0.f;
                if (BIAS_RELU) { bv0 = bias[col]; bv1 = bias[col + 1]; }
#pragma unroll
                for (int h = 0; h < 2; h++) {
                    int row = bm + wm * 32 + mi * 16 + (lane >> 2) + h * 8;
                    if (row < NN) {
                        float v0 = acc[mi][ni][2 * h];
                        float v1 = acc[mi][ni][2 * h + 1];
                        if (BIAS_RELU) {
                            v0 = fmaxf(v0 + bv0, 0.0f);
                            v1 = fmaxf(v1 + bv1, 0.0f);
                        }
                        if (OUTH) {
                            __half2 p = __floats2half2_rn(v0, v1);
                            *(__half2*)&((__half*)Cv)[(long long)row * M + col] = p;
                        } else {
                            *(float2*)&((float*)Cv)[(long long)row * M + col] = make_float2(v0, v1);
                        }
                    }
                }
            }
        }
    }
}

// ---------------- fused Wc1 + relu + proj3 -------------------------------------
#define WP_PIPE_BYTES 54272
#define WP_SMEM_BYTES 121856

__global__ void __launch_bounds__(512)
wc1_proj_kernel(const __half* __restrict__ A,      // h2a [NN,256]
                const __half* __restrict__ W1,     // Wc1 [256,256] half
                const float* __restrict__ b1,      // bc1 [256]
                const __half* __restrict__ Wp,     // padded We3 [256,64] half
                __half* __restrict__ P) {          // p64h [NN,64]
    gdc_wait();
    extern __shared__ __align__(16) unsigned char dsm[];
    __half* As0 = (__half*)dsm;                         // 2 stages 128x40
    __half* Bs0 = (__half*)(dsm + 2 * 128 * 40 * 2);    // 2 stages 32x264
    __half* Wps = (__half*)dsm;                         // phase2: 256x72
    __half* Hs  = (__half*)(dsm + WP_PIPE_BYTES);       // 128x264

    const int t = threadIdx.x;
    const int lane = t & 31;
    const int warp = t >> 5;       // 0..15
    const int wm = warp & 3;       // 4 row slabs x32
    const int wn = warp >> 2;      // 4 col slabs x64
    const int bm = blockIdx.x * 128;

    float acc[2][8][4];
#pragma unroll
    for (int mi = 0; mi < 2; mi++)
#pragma unroll
        for (int ni = 0; ni < 8; ni++)
#pragma unroll
            for (int r = 0; r < 4; r++) acc[mi][ni][r] = 0.0f;

    const int arow = t >> 2, ac = (t & 3) * 8;

    auto stage = [&](int s, int buf) {
        __half* As = As0 + buf * 128 * 40;
        __half* Bs = Bs0 + buf * 32 * 264;
        int k0 = s * 32;
        {
            int grow = bm + arow; if (grow > NN - 1) grow = NN - 1;
            cp16(smem_u32(&As[arow * 40 + ac]), &A[(long long)grow * 256 + k0 + ac]);
        }
#pragma unroll
        for (int r = 0; r < 2; r++) {
            int idx = t + r * 512;
            int kk = idx >> 5, c8 = (idx & 31) * 8;
            cp16(smem_u32(&Bs[kk * 264 + c8]), &W1[(long long)(k0 + kk) * 256 + c8]);
        }
    };

    stage(0, 0);
    cp_commit();

    for (int s = 0; s < 8; s++) {
        if (s + 1 < 8) {
            stage(s + 1, (s + 1) & 1);
            cp_commit();
            cp_wait<1>();
        } else {
            cp_wait<0>();
        }
        __syncthreads();
        const __half* As = As0 + (s & 1) * 128 * 40;
        const __half* Bs = Bs0 + (s & 1) * 32 * 264;
#pragma unroll
        for (int ks = 0; ks < 2; ks++) {
            unsigned a[2][4], b[8][2];
#pragma unroll
            for (int mi = 0; mi < 2; mi++) {
                int row = wm * 32 + mi * 16 + (lane & 15);
                int col = ks * 16 + (lane >> 4) * 8;
                ldsm_x4(a[mi][0], a[mi][1], a[mi][2], a[mi][3], smem_u32(&As[row * 40 + col]));
            }
#pragma unroll
            for (int p = 0; p < 4; p++) {
                int row = ks * 16 + ((lane >> 3) & 1) * 8 + (lane & 7);
                int col = wn * 64 + p * 16 + (lane >> 4) * 8;
                ldsm_x4_t(b[2 * p][0], b[2 * p][1], b[2 * p + 1][0], b[2 * p + 1][1],
                          smem_u32(&Bs[row * 264 + col]));
            }
#pragma unroll
            for (int mi = 0; mi < 2; mi++)
#pragma unroll
                for (int ni = 0; ni < 8; ni++)
                    mma_f16(acc[mi][ni], a[mi], b[ni]);
        }
        __syncthreads();
    }

    // phase boundary: relu(acc + bias) -> Hs (half)
#pragma unroll
    for (int mi = 0; mi < 2; mi++) {
#pragma unroll
        for (int ni = 0; ni < 8; ni++) {
            int col = wn * 64 + ni * 8 + 2 * (lane & 3);
            float bv0 = b1[col], bv1 = b1[col + 1];
#pragma unroll
            for (int h = 0; h < 2; h++) {
                int row = wm * 32 + mi * 16 + (lane >> 2) + h * 8;
                float v0 = fmaxf(acc[mi][ni][2 * h] + bv0, 0.0f);
                float v1 = fmaxf(acc[mi][ni][2 * h + 1] + bv1, 0.0f);
                *(__half2*)&Hs[row * 264 + col] = __floats2half2_rn(v0, v1);
            }
        }
    }
    __syncthreads();

    // stage Wp3 [256,64] into Wps (stride 72) — pipe region free now
#pragma unroll
    for (int r = 0; r < 4; r++) {
        int idx = t + r * 512;
        int kk = idx >> 3, c8 = (idx & 7) * 8;
        cp16(smem_u32(&Wps[kk * 72 + c8]), &Wp[(long long)kk * 64 + c8]);
    }
    cp_commit();
    cp_wait<0>();
    __syncthreads();

    // phase 2: H @ Wp3 -> P
    const int wm2 = warp & 7;      // 8 row groups x16
    const int wn2 = warp >> 3;     // 2 col groups x32
    float acc2[4][4];
#pragma unroll
    for (int ni = 0; ni < 4; ni++)
#pragma unroll
        for (int r = 0; r < 4; r++) acc2[ni][r] = 0.0f;

#pragma unroll
    for (int kc = 0; kc < 16; kc++) {
        unsigned a[4], b[4][2];
        {
            int row = wm2 * 16 + (lane & 15);
            int col = kc * 16 + (lane >> 4) * 8;
            ldsm_x4(a[0], a[1], a[2], a[3], smem_u32(&Hs[row * 264 + col]));
        }
#pragma unroll
        for (int p = 0; p < 2; p++) {
            int row = kc * 16 + ((lane >> 3) & 1) * 8 + (lane & 7);
            int col = wn2 * 32 + p * 16 + (lane >> 4) * 8;
            ldsm_x4_t(b[2 * p][0], b[2 * p][1], b[2 * p + 1][0], b[2 * p + 1][1],
                      smem_u32(&Wps[row * 72 + col]));
        }
#pragma unroll
        for (int ni = 0; ni < 4; ni++)
            mma_f16(acc2[ni], a, b[ni]);
    }

#pragma unroll
    for (int ni = 0; ni < 4; ni++) {
        int col = wn2 * 32 + ni * 8 + 2 * (lane & 3);
#pragma unroll
        for (int h = 0; h < 2; h++) {
            int row = bm + wm2 * 16 + (lane >> 2) + h * 8;
            if (row < NN) {
                *(__half2*)&P[(long long)row * 64 + col] =
                    __floats2half2_rn(acc2[ni][2 * h], acc2[ni][2 * h + 1]);
            }
        }
    }
}

// ---------------- last layer: half 40-dim aggregate + bias + log_softmax ------
__global__ void agg40h_kernel(const __half* __restrict__ P, const float* __restrict__ bias,
                              float* __restrict__ out) {
    gdc_wait();
    int gid = blockIdx.x * (blockDim.x >> 3) + (threadIdx.x >> 3);
    int t = threadIdx.x & 7;
    bool valid = gid < NN;
    bool cvalid = t < 5;
    float v[8];
#pragma unroll
    for (int i = 0; i < 8; i++) v[i] = 0.0f;
    const uint4* Pv = (const uint4*)P;
    int beg = 0, end = 0;
    float dinv0 = 0.0f;
    if (valid) {
        dinv0 = g_dinv[gid];
        uint4 u = Pv[gid * 8 + t];
        acc_u4(v, u, dinv0);
        beg = g_rowptr[gid];
        end = g_rowptr[gid + 1];
    }
    int j = beg;
    for (; j + 3 < end; j += 4) {
        int s0 = g_csr[j],     s1 = g_csr[j + 1];
        int s2 = g_csr[j + 2], s3 = g_csr[j + 3];
        float c0 = __ldg(&g_dinv[s0]);
        float c1 = __ldg(&g_dinv[s1]);
        float c2 = __ldg(&g_dinv[s2]);
        float c3 = __ldg(&g_dinv[s3]);
        uint4 u0 = __ldg(&Pv[s0 * 8 + t]);
        uint4 u1 = __ldg(&Pv[s1 * 8 + t]);
        uint4 u2 = __ldg(&Pv[s2 * 8 + t]);
        uint4 u3 = __ldg(&Pv[s3 * 8 + t]);
        acc_u4(v, u0, c0);
        acc_u4(v, u1, c1);
        acc_u4(v, u2, c2);
        acc_u4(v, u3, c3);
    }
    for (; j < end; j++) {
        int s = g_csr[j];
        float c = __ldg(&g_dinv[s]);
        uint4 u = __ldg(&Pv[s * 8 + t]);
        acc_u4(v, u, c);
    }
    float m = -1e30f;
    if (cvalid) {
#pragma unroll
        for (int i = 0; i < 8; i++) {
            v[i] = v[i] * dinv0 + bias[8 * t + i];
            m = fmaxf(m, v[i]);
        }
    }
#pragma unroll
    for (int o = 1; o < 8; o <<= 1) m = fmaxf(m, __shfl_xor_sync(0xffffffffu, m, o));
    float s = 0.0f;
    if (cvalid) {
#pragma unroll
        for (int i = 0; i < 8; i++) s += expf(v[i] - m);
    }
#pragma unroll
    for (int o = 1; o < 8; o <<= 1) s += __shfl_xor_sync(0xffffffffu, s, o);
    float lse = m + logf(s);
    if (valid && cvalid) {
        float* op = out + (long long)gid * 160 + 120 + 8 * t;
        *(float4*)&op[0] = make_float4(v[0] - lse, v[1] - lse, v[2] - lse, v[3] - lse);
        *(float4*)&op[4] = make_float4(v[4] - lse, v[5] - lse, v[6] - lse, v[7] - lse);
    }
}

// ---------------- PDL launch helper ---------------------------------------------
template <typename Kern, typename... Args>
static void launch_pdl(Kern kern, dim3 grid, dim3 block, size_t smem, cudaStream_t st,
                       Args... args) {
    cudaLaunchConfig_t cfg = {};
    cfg.gridDim = grid;
    cfg.blockDim = block;
    cfg.dynamicSmemBytes = smem;
    cfg.stream = st;
    cudaLaunchAttribute at[1];
    at[0].id = cudaLaunchAttributeProgrammaticStreamSerialization;
    at[0].val.programmaticStreamSerializationAllowed = 1;
    cfg.attrs = at;
    cfg.numAttrs = 1;
    cudaLaunchKernelEx(&cfg, kern, args...);
}

// ---------------- launch -------------------------------------------------------
extern "C" void kernel_launch(void* const* d_in, const int* in_sizes, int n_in,
                              void* d_out, int out_size) {
    const float* x   = (const float*)d_in[0];
    const void*  ei  = d_in[1];
    const float* Wc0 = (const float*)d_in[2];
    const float* bc0 = (const float*)d_in[3];
    const float* Wc1 = (const float*)d_in[4];
    const float* bc1 = (const float*)d_in[5];
    // d_in[6], d_in[7] (Wc2, bc2): dead — final Wc output is never used
    const float* We0 = (const float*)d_in[8];
    const float* be0 = (const float*)d_in[9];
    const float* We1 = (const float*)d_in[10];
    const float* be1 = (const float*)d_in[11];
    const float* We2 = (const float*)d_in[12];
    const float* be2 = (const float*)d_in[13];
    const float* We3 = (const float*)d_in[14];
    const float* be3 = (const float*)d_in[15];
    float* out = (float*)d_out;
    int E = in_sizes[1] / 2;

    __half *xh, *h1h, *h2h, *h2ah, *p64h, *wph, *wc0h, *wc1h;
    cudaGetSymbolAddress((void**)&xh,   g_xh);
    cudaGetSymbolAddress((void**)&h1h,  g_h1h);
    cudaGetSymbolAddress((void**)&h2h,  g_h2h);
    cudaGetSymbolAddress((void**)&h2ah, g_h2ah);
    cudaGetSymbolAddress((void**)&p64h, g_p64h);
    cudaGetSymbolAddress((void**)&wph,  g_Wph);
    cudaGetSymbolAddress((void**)&wc0h, g_Wc0h);
    cudaGetSymbolAddress((void**)&wc1h, g_Wc1h);
    __half* wp0 = wph;
    __half* wp1 = wph + 1 * 256 * 64;
    __half* wp2 = wph + 2 * 256 * 64;
    __half* wp3 = wph + 3 * 256 * 64;

    // allow >48KB dynamic smem for the fused kernel (host attr set; not captured)
    cudaFuncSetAttribute(wc1_proj_kernel, cudaFuncAttributeMaxDynamicSharedMemorySize,
                         WP_SMEM_BYTES);

    static cudaStream_t s1 = nullptr;
    static cudaEvent_t evStart, evPre, evA1, evA2, evS1;
    if (!s1) {
        cudaStreamCreateWithFlags(&s1, cudaStreamNonBlocking);
        cudaEventCreateWithFlags(&evStart, cudaEventDisableTiming);
        cudaEventCreateWithFlags(&evPre,   cudaEventDisableTiming);
        cudaEventCreateWithFlags(&evA1,    cudaEventDisableTiming);
        cudaEventCreateWithFlags(&evA2,    cudaEventDisableTiming);
        cudaEventCreateWithFlags(&evS1,    cudaEventDisableTiming);
    }

    int nb = (NN + 1023) / 1024;
    dim3 g1((NN + 127) / 128, 1);
    dim3 g4((NN + 127) / 128, 4);
    int  gs = (NN + 31) / 32;

    cudaEventRecord(evStart, 0);
    cudaStreamWaitEvent(s1, evStart, 0);

    // s1: all weight/feature prep in ONE kernel, then fused layer-0 projection
    prep_all_kernel<<<12788, 256, 0, s1>>>(x, Wc0, Wc1, We0, We1, We2, We3);
    cudaEventRecord(evPre, s1);
    hgemm_kernel<128, 64, false, false, true, false><<<g1, 256, 0, s1>>>(
        xh, wp0, be0, nullptr, out, 0);

    // main: CSR preprocessing (overlaps s1) — PDL chain
    init_kernel<<<(NN + 255) / 256, 256>>>((const int*)ei);
    launch_pdl(count_kernel, dim3((E / 2 + 255) / 256), dim3(256), 0, (cudaStream_t)0, ei, E);
    launch_pdl(scan1_kernel, dim3(nb), dim3(1024), 0, (cudaStream_t)0);
    launch_pdl(scan23_kernel, dim3((NN + 255) / 256), dim3(256), 0, (cudaStream_t)0, nb);
    launch_pdl(fill_kernel, dim3((E / 2 + 255) / 256), dim3(256), 0, (cudaStream_t)0, ei, E);

    // main chain — PDL between successive stages
    cudaStreamWaitEvent(0, evPre, 0);
    launch_pdl(agg_u4_kernel<16>, dim3((NN * 16 + 255) / 256), dim3(256), 0, (cudaStream_t)0,
               (const __half*)xh, h1h);                                   // D=128
    cudaEventRecord(evA1, 0);
    launch_pdl(hgemm_kernel<128, 256, true, true, false, true>, g4, dim3(256), 0, (cudaStream_t)0,
               (const __half*)h1h, (const __half*)wc0h, bc0, (void*)h2h, (float*)nullptr, 0);
    launch_pdl(agg_u4_kernel<32>, dim3((NN * 32 + 255) / 256), dim3(256), 0, (cudaStream_t)0,
               (const __half*)h2h, h2ah);                                 // D=256
    cudaEventRecord(evA2, 0);
    launch_pdl(wc1_proj_kernel, dim3((NN + 127) / 128), dim3(512), WP_SMEM_BYTES, (cudaStream_t)0,
               (const __half*)h2ah, (const __half*)wc1h, bc1, (const __half*)wp3, p64h);
    launch_pdl(agg40h_kernel, dim3(gs), dim3(256), 0, (cudaStream_t)0,
               (const __half*)p64h, be3, out);

    // s1: fused projection layers 1/2 overlap the Wc GEMMs / aggs
    cudaStreamWaitEvent(s1, evA1, 0);
    hgemm_kernel<128, 64, false, false, true, false><<<g1, 256, 0, s1>>>(
        h1h, wp1, be1, nullptr, out, 1);
    cudaStreamWaitEvent(s1, evA2, 0);
    hgemm_kernel<256, 64, false, false, true, false><<<g1, 256, 0, s1>>>(
        h2ah, wp2, be2, nullptr, out, 2);
    cudaEventRecord(evS1, s1);

    cudaStreamWaitEvent(0, evS1, 0);
}